// round 1
// baseline (speedup 1.0000x reference)
#include <cuda_runtime.h>
#include <math.h>

// Problem constants
#define NB    2
#define NS    2048
#define NDIM  2048
#define NH    16
#define NKVH  4
#define NHD   128
#define NHEFF 192          // effective attended head dim after the reference's rope concat
#define NWIN  1024
#define SCALE_F 0.08838834764831845f   // 128^-0.5

#define NM (NB*NS)         // 4096 rows for all GEMMs

// ---------------- scratch (static device allocations; no cudaMalloc) ----------------
__device__ float g_Qraw[(size_t)NM * (NH*NHD)];        // 4096 x 2048
__device__ float g_Kraw[(size_t)NM * (NKVH*NHD)];      // 4096 x 512
__device__ float g_Vraw[(size_t)NM * (NKVH*NHD)];      // 4096 x 512
__device__ float g_Q192[(size_t)NB*NH*NS*NHEFF];       // [b][h][s][192]
__device__ float g_K192[(size_t)NB*NKVH*NS*NHEFF];     // [b][kv][s][192]
__device__ float g_Vt  [(size_t)NB*NKVH*NS*NHD];       // [b][kv][s][128]
__device__ float g_O   [(size_t)NM * (NH*NHD)];        // 4096 x 2048 (b,s,h,d)

// ---------------- generic fp32 SGEMM: C = A(MxK,row) * B(KxN,row) ----------------
// 128x128 block, BK=8, 256 threads, 8x8 microtile with 4+4 split rows/cols.
__global__ __launch_bounds__(256) void sgemm128(const float* __restrict__ A,
                                                const float* __restrict__ Bw,
                                                float* __restrict__ C,
                                                int M, int N, int K)
{
    __shared__ float As[8][128];
    __shared__ float Bs[8][128];
    const int tid = threadIdx.x;
    const int m0 = blockIdx.y * 128;
    const int n0 = blockIdx.x * 128;
    const int tx = tid & 15;
    const int ty = tid >> 4;
    const int ar = tid >> 1,  ac = (tid & 1) * 4;   // A: 128 rows x 8 k
    const int br = tid >> 5,  bc = (tid & 31) * 4;  // B: 8 rows x 128 n

    const float* Ap = A  + (size_t)(m0 + ar) * K + ac;
    const float* Bp = Bw + (size_t)br * N + n0 + bc;

    float acc[8][8];
#pragma unroll
    for (int i = 0; i < 8; i++)
#pragma unroll
        for (int j = 0; j < 8; j++) acc[i][j] = 0.f;

    for (int k0 = 0; k0 < K; k0 += 8) {
        float4 av = *(const float4*)(Ap + k0);
        float4 bv = *(const float4*)(Bp + (size_t)k0 * N);
        __syncthreads();
        As[ac + 0][ar] = av.x; As[ac + 1][ar] = av.y;
        As[ac + 2][ar] = av.z; As[ac + 3][ar] = av.w;
        *(float4*)&Bs[br][bc] = bv;
        __syncthreads();
#pragma unroll
        for (int kk = 0; kk < 8; kk++) {
            float a[8], b[8];
            *(float4*)&a[0] = *(const float4*)&As[kk][ty * 4];
            *(float4*)&a[4] = *(const float4*)&As[kk][64 + ty * 4];
            *(float4*)&b[0] = *(const float4*)&Bs[kk][tx * 4];
            *(float4*)&b[4] = *(const float4*)&Bs[kk][64 + tx * 4];
#pragma unroll
            for (int i = 0; i < 8; i++)
#pragma unroll
                for (int j = 0; j < 8; j++) acc[i][j] += a[i] * b[j];
        }
    }
#pragma unroll
    for (int i = 0; i < 8; i++) {
        int row = m0 + ((i < 4) ? (ty * 4 + i) : (64 + ty * 4 + (i - 4)));
        float4 c0 = make_float4(acc[i][0], acc[i][1], acc[i][2], acc[i][3]);
        float4 c1 = make_float4(acc[i][4], acc[i][5], acc[i][6], acc[i][7]);
        *(float4*)&C[(size_t)row * N + n0 + tx * 4]      = c0;
        *(float4*)&C[(size_t)row * N + n0 + 64 + tx * 4] = c1;
    }
}

// ---------------- RoPE + layout repack ----------------
// Reference: q_out = concat([qr*(c-s), qr*(c+s), qi]) -> 192 dims. Same for K. V copied.
__global__ __launch_bounds__(256) void rope_pack(const float* __restrict__ cosb,
                                                 const float* __restrict__ sinb)
{
    int idx = blockIdx.x * 256 + threadIdx.x;
    // Q: NB*NS*NH*64 = 4194304 threads
    if (idx < NB * NS * NH * 64) {
        int d = idx & 63, h = (idx >> 6) & 15, s = (idx >> 10) & 2047, b = idx >> 21;
        float c = cosb[s * 64 + d], sn = sinb[s * 64 + d];
        const float* qp = g_Qraw + (size_t)(b * NS + s) * (NH * NHD) + h * NHD;
        float qr = qp[d], qi = qp[64 + d];
        float* qo = g_Q192 + ((size_t)(b * NH + h) * NS + s) * NHEFF;
        qo[d]       = qr * (c - sn);
        qo[64 + d]  = qr * (c + sn);
        qo[128 + d] = qi;
    }
    // K: NB*NS*NKVH*64 = 1048576
    if (idx < NB * NS * NKVH * 64) {
        int d = idx & 63, kv = (idx >> 6) & 3, s = (idx >> 8) & 2047, b = idx >> 19;
        float c = cosb[s * 64 + d], sn = sinb[s * 64 + d];
        const float* kp = g_Kraw + (size_t)(b * NS + s) * (NKVH * NHD) + kv * NHD;
        float kr = kp[d], ki = kp[64 + d];
        float* ko = g_K192 + ((size_t)(b * NKVH + kv) * NS + s) * NHEFF;
        ko[d]       = kr * (c - sn);
        ko[64 + d]  = kr * (c + sn);
        ko[128 + d] = ki;
    }
    // V: NB*NS*NKVH*128 = 2097152
    if (idx < NB * NS * NKVH * 128) {
        int d = idx & 127, kv = (idx >> 7) & 3, s = (idx >> 9) & 2047, b = idx >> 20;
        g_Vt[((size_t)(b * NKVH + kv) * NS + s) * NHD + d] =
            g_Vraw[(size_t)(b * NS + s) * (NKVH * NHD) + kv * NHD + d];
    }
}

// ---------------- windowed flash attention ----------------
// Block: 64 q-rows x full head. 256 threads (tx=0..15 over k/d cols, ty=0..15 over q rows).
// Shared layouts (transposed k-major for S-gemm): Qst[192][68], Kst[192][68], Vs[64][132], Ps[64][64]
#define QK_STR 68
#define V_STR  132
#define SMEM_ATTN_FLOATS (192*QK_STR*2 + 64*V_STR + 64*64)
#define SMEM_ATTN_BYTES  (SMEM_ATTN_FLOATS * 4)

__global__ __launch_bounds__(256) void attn_kernel()
{
    extern __shared__ float sm[];
    float* Qst = sm;                       // [192][68]
    float* Kst = Qst + 192 * QK_STR;       // [192][68]
    float* Vs  = Kst + 192 * QK_STR;       // [64][132]
    float* Ps  = Vs + 64 * V_STR;          // [64][64]

    const int tid = threadIdx.x;
    const int tx = tid & 15, ty = tid >> 4;
    const int qt = blockIdx.x;             // 0..31
    const int bh = blockIdx.y;             // 0..31
    const int b = bh >> 4, h = bh & 15, kv = h >> 2;
    const int qbase = qt * 64;

    // Load Q tile transposed: global [r][192] -> shared [k][r]
    {
        const float* Qg = g_Q192 + ((size_t)(b * NH + h) * NS + qbase) * NHEFF;
#pragma unroll 4
        for (int i = tid; i < 64 * NHEFF; i += 256) {
            int r = i / NHEFF, k = i - r * NHEFF;
            Qst[k * QK_STR + r] = Qg[i];
        }
    }

    float mo[4], l[4], o[4][8];
#pragma unroll
    for (int i = 0; i < 4; i++) {
        mo[i] = -1e30f; l[i] = 0.f;
#pragma unroll
        for (int j = 0; j < 8; j++) o[i][j] = 0.f;
    }

    const int kt0 = (qt > 16) ? (qt - 16) : 0;
    for (int kt = kt0; kt <= qt; kt++) {
        const int kbase = kt * 64;
        const float* Kg = g_K192 + ((size_t)(b * NKVH + kv) * NS + kbase) * NHEFF;
        const float* Vg = g_Vt   + ((size_t)(b * NKVH + kv) * NS + kbase) * NHD;

        __syncthreads();  // previous PV done (and Qst ready on first iter)
#pragma unroll 4
        for (int i = tid; i < 64 * NHEFF; i += 256) {
            int r = i / NHEFF, k = i - r * NHEFF;
            Kst[k * QK_STR + r] = Kg[i];
        }
#pragma unroll 2
        for (int i = tid; i < 64 * 32; i += 256) {
            int r = i >> 5, c = (i & 31) * 4;
            *(float4*)&Vs[r * V_STR + c] = *(const float4*)&Vg[r * NHD + c];
        }
        __syncthreads();

        // S = Q @ K^T (4x4 per thread over 192 dims)
        float s4[4][4];
#pragma unroll
        for (int i = 0; i < 4; i++)
#pragma unroll
            for (int j = 0; j < 4; j++) s4[i][j] = 0.f;
#pragma unroll 4
        for (int k = 0; k < NHEFF; k++) {
            float4 av = *(const float4*)&Qst[k * QK_STR + ty * 4];
            float4 bv = *(const float4*)&Kst[k * QK_STR + tx * 4];
            s4[0][0] += av.x * bv.x; s4[0][1] += av.x * bv.y; s4[0][2] += av.x * bv.z; s4[0][3] += av.x * bv.w;
            s4[1][0] += av.y * bv.x; s4[1][1] += av.y * bv.y; s4[1][2] += av.y * bv.z; s4[1][3] += av.y * bv.w;
            s4[2][0] += av.z * bv.x; s4[2][1] += av.z * bv.y; s4[2][2] += av.z * bv.z; s4[2][3] += av.z * bv.w;
            s4[3][0] += av.w * bv.x; s4[3][1] += av.w * bv.y; s4[3][2] += av.w * bv.z; s4[3][3] += av.w * bv.w;
        }

        // masked online softmax (window: k<=q && k>q-1024)
#pragma unroll
        for (int i = 0; i < 4; i++) {
            int q = qbase + ty * 4 + i;
            float rm = -1e30f;
#pragma unroll
            for (int j = 0; j < 4; j++) {
                int kk2 = kbase + tx * 4 + j;
                float sv = (kk2 <= q && kk2 + NWIN > q) ? s4[i][j] * SCALE_F : -1e30f;
                s4[i][j] = sv;
                rm = fmaxf(rm, sv);
            }
            rm = fmaxf(rm, __shfl_xor_sync(0xffffffffu, rm, 8));
            rm = fmaxf(rm, __shfl_xor_sync(0xffffffffu, rm, 4));
            rm = fmaxf(rm, __shfl_xor_sync(0xffffffffu, rm, 2));
            rm = fmaxf(rm, __shfl_xor_sync(0xffffffffu, rm, 1));
            float mn = fmaxf(mo[i], rm);
            float f = __expf(mo[i] - mn);
            mo[i] = mn;
            float rs = 0.f;
#pragma unroll
            for (int j = 0; j < 4; j++) {
                float p = (s4[i][j] > -1e29f) ? __expf(s4[i][j] - mn) : 0.f;
                s4[i][j] = p; rs += p;
            }
            rs += __shfl_xor_sync(0xffffffffu, rs, 8);
            rs += __shfl_xor_sync(0xffffffffu, rs, 4);
            rs += __shfl_xor_sync(0xffffffffu, rs, 2);
            rs += __shfl_xor_sync(0xffffffffu, rs, 1);
            l[i] = l[i] * f + rs;
#pragma unroll
            for (int j = 0; j < 8; j++) o[i][j] *= f;
            *(float4*)&Ps[(ty * 4 + i) * 64 + tx * 4] =
                make_float4(s4[i][0], s4[i][1], s4[i][2], s4[i][3]);
        }
        __syncthreads();

        // O += P @ V  (4 rows x (4+4) cols per thread)
#pragma unroll 2
        for (int k = 0; k < 64; k++) {
            float p0 = Ps[(ty * 4 + 0) * 64 + k];
            float p1 = Ps[(ty * 4 + 1) * 64 + k];
            float p2 = Ps[(ty * 4 + 2) * 64 + k];
            float p3 = Ps[(ty * 4 + 3) * 64 + k];
            float4 v0 = *(const float4*)&Vs[k * V_STR + tx * 4];
            float4 v1 = *(const float4*)&Vs[k * V_STR + 64 + tx * 4];
            o[0][0] += p0 * v0.x; o[0][1] += p0 * v0.y; o[0][2] += p0 * v0.z; o[0][3] += p0 * v0.w;
            o[0][4] += p0 * v1.x; o[0][5] += p0 * v1.y; o[0][6] += p0 * v1.z; o[0][7] += p0 * v1.w;
            o[1][0] += p1 * v0.x; o[1][1] += p1 * v0.y; o[1][2] += p1 * v0.z; o[1][3] += p1 * v0.w;
            o[1][4] += p1 * v1.x; o[1][5] += p1 * v1.y; o[1][6] += p1 * v1.z; o[1][7] += p1 * v1.w;
            o[2][0] += p2 * v0.x; o[2][1] += p2 * v0.y; o[2][2] += p2 * v0.z; o[2][3] += p2 * v0.w;
            o[2][4] += p2 * v1.x; o[2][5] += p2 * v1.y; o[2][6] += p2 * v1.z; o[2][7] += p2 * v1.w;
            o[3][0] += p3 * v0.x; o[3][1] += p3 * v0.y; o[3][2] += p3 * v0.z; o[3][3] += p3 * v0.w;
            o[3][4] += p3 * v1.x; o[3][5] += p3 * v1.y; o[3][6] += p3 * v1.z; o[3][7] += p3 * v1.w;
        }
    }

    // epilogue: normalize and write O in (b, s, h, d) layout for the final GEMM
#pragma unroll
    for (int i = 0; i < 4; i++) {
        int q = qbase + ty * 4 + i;
        float inv = 1.0f / l[i];
        size_t rowbase = (size_t)(b * NS + q) * (NH * NHD) + h * NHD;
        *(float4*)&g_O[rowbase + tx * 4] =
            make_float4(o[i][0] * inv, o[i][1] * inv, o[i][2] * inv, o[i][3] * inv);
        *(float4*)&g_O[rowbase + 64 + tx * 4] =
            make_float4(o[i][4] * inv, o[i][5] * inv, o[i][6] * inv, o[i][7] * inv);
    }
}

// ---------------- launch ----------------
extern "C" void kernel_launch(void* const* d_in, const int* in_sizes, int n_in,
                              void* d_out, int out_size)
{
    (void)in_sizes; (void)n_in; (void)out_size;
    const float* x    = (const float*)d_in[0];
    const float* cosb = (const float*)d_in[1];
    const float* sinb = (const float*)d_in[2];
    // d_in[3] = positions (unused), d_in[4] = mask (window computed analytically)
    const float* wq   = (const float*)d_in[5];
    const float* wk   = (const float*)d_in[6];
    const float* wv   = (const float*)d_in[7];
    const float* wo   = (const float*)d_in[8];
    float* out = (float*)d_out;

    float *Qraw, *Kraw, *Vraw, *O;
    cudaGetSymbolAddress((void**)&Qraw, g_Qraw);
    cudaGetSymbolAddress((void**)&Kraw, g_Kraw);
    cudaGetSymbolAddress((void**)&Vraw, g_Vraw);
    cudaGetSymbolAddress((void**)&O,    g_O);

    static bool attr_done = false;  // attribute is sticky per-process; value never changes
    if (!attr_done) {
        cudaFuncSetAttribute(attn_kernel, cudaFuncAttributeMaxDynamicSharedMemorySize,
                             SMEM_ATTN_BYTES);
        attr_done = true;
    }

    // QKV projections
    sgemm128<<<dim3(NH*NHD/128,   NM/128), 256>>>(x, wq, Qraw, NM, NH*NHD,   NDIM);
    sgemm128<<<dim3(NKVH*NHD/128, NM/128), 256>>>(x, wk, Kraw, NM, NKVH*NHD, NDIM);
    sgemm128<<<dim3(NKVH*NHD/128, NM/128), 256>>>(x, wv, Vraw, NM, NKVH*NHD, NDIM);

    // RoPE + repack
    rope_pack<<<(NB*NS*NH*64 + 255) / 256, 256>>>(cosb, sinb);

    // windowed attention
    attn_kernel<<<dim3(NS/64, NB*NH), 256, SMEM_ATTN_BYTES>>>();

    // output projection
    sgemm128<<<dim3(NDIM/128, NM/128), 256>>>(O, wo, out, NM, NDIM, NH*NHD);
}

// round 4
// speedup vs baseline: 1.5015x; 1.5015x over previous
#include <cuda_runtime.h>
#include <cuda_bf16.h>
#include <math.h>
#include <stdint.h>

// Problem constants
#define NB    2
#define NS    2048
#define NDIM  2048
#define NH    16
#define NKVH  4
#define NHD   128
#define NHEFF 192
#define NWIN  1024
#define SCALE_F 0.08838834764831845f

#define NM (NB*NS)

// ---------------- scratch ----------------
__device__ float g_Qraw[(size_t)NM * (NH*NHD)];
__device__ float g_Kraw[(size_t)NM * (NKVH*NHD)];
__device__ float g_Vraw[(size_t)NM * (NKVH*NHD)];
__device__ float g_Q192[(size_t)NB*NH*NS*NHEFF];
__device__ float g_K192[(size_t)NB*NKVH*NS*NHEFF];
__device__ float g_Vt  [(size_t)NB*NKVH*NS*NHD];
__device__ float g_O   [(size_t)NM * (NH*NHD)];

// bf16 hi/lo split operands for tensor-core GEMMs
__device__ __nv_bfloat16 g_xhi[(size_t)NM * NDIM];
__device__ __nv_bfloat16 g_xlo[(size_t)NM * NDIM];
__device__ __nv_bfloat16 g_Ohi[(size_t)NM * (NH*NHD)];
__device__ __nv_bfloat16 g_Olo[(size_t)NM * (NH*NHD)];
__device__ __nv_bfloat16 g_wqthi[(size_t)(NH*NHD) * NDIM];   // [N][K]
__device__ __nv_bfloat16 g_wqtlo[(size_t)(NH*NHD) * NDIM];
__device__ __nv_bfloat16 g_wkthi[(size_t)(NKVH*NHD) * NDIM];
__device__ __nv_bfloat16 g_wktlo[(size_t)(NKVH*NHD) * NDIM];
__device__ __nv_bfloat16 g_wvthi[(size_t)(NKVH*NHD) * NDIM];
__device__ __nv_bfloat16 g_wvtlo[(size_t)(NKVH*NHD) * NDIM];
__device__ __nv_bfloat16 g_wothi[(size_t)NDIM * (NH*NHD)];   // [N=DIM][K=H*HD]
__device__ __nv_bfloat16 g_wotlo[(size_t)NDIM * (NH*NHD)];

// ---------------- portable PTX helpers (no sm_103a-only features) ----------------
__device__ __forceinline__ uint32_t smem_u32(const void* p) {
    uint32_t a;
    asm("{ .reg .u64 t; cvta.to.shared.u64 t, %1; cvt.u32.u64 %0, t; }" : "=r"(a) : "l"(p));
    return a;
}
__device__ __forceinline__ void cp16(uint32_t dst, const void* src) {
    asm volatile("cp.async.cg.shared.global [%0], [%1], 16;" :: "r"(dst), "l"(src));
}
__device__ __forceinline__ void ldm_x4(uint32_t& r0, uint32_t& r1, uint32_t& r2, uint32_t& r3,
                                       uint32_t addr) {
    asm volatile("ldmatrix.sync.aligned.m8n8.x4.shared.b16 {%0,%1,%2,%3}, [%4];"
                 : "=r"(r0), "=r"(r1), "=r"(r2), "=r"(r3) : "r"(addr));
}
__device__ __forceinline__ void mma_bf16(float* d, const uint32_t* a, uint32_t b0, uint32_t b1) {
    asm volatile(
        "mma.sync.aligned.m16n8k16.row.col.f32.bf16.bf16.f32 "
        "{%0,%1,%2,%3}, {%4,%5,%6,%7}, {%8,%9}, {%0,%1,%2,%3};"
        : "+f"(d[0]), "+f"(d[1]), "+f"(d[2]), "+f"(d[3])
        : "r"(a[0]), "r"(a[1]), "r"(a[2]), "r"(a[3]), "r"(b0), "r"(b1));
}

// ---------------- conversion kernels ----------------
__global__ __launch_bounds__(256) void cvt_hi_lo(const float* __restrict__ in,
                                                 __nv_bfloat16* __restrict__ hi,
                                                 __nv_bfloat16* __restrict__ lo, int n)
{
    int i = blockIdx.x * 256 + threadIdx.x;
    if (i < n) {
        float v = in[i];
        __nv_bfloat16 h = __float2bfloat16(v);
        hi[i] = h;
        lo[i] = __float2bfloat16(v - __bfloat162float(h));
    }
}

// transpose-convert: W[K][N] f32 -> Thi/Tlo[N][K] bf16
__global__ __launch_bounds__(256) void cvt_w_t(const float* __restrict__ W,
                                               __nv_bfloat16* __restrict__ Thi,
                                               __nv_bfloat16* __restrict__ Tlo,
                                               int K, int N)
{
    __shared__ float t[32][33];
    int n0 = blockIdx.x * 32, k0 = blockIdx.y * 32;
    int tx = threadIdx.x & 31, ty = threadIdx.x >> 5;
#pragma unroll
    for (int i = ty; i < 32; i += 8)
        t[i][tx] = W[(size_t)(k0 + i) * N + n0 + tx];
    __syncthreads();
#pragma unroll
    for (int i = ty; i < 32; i += 8) {
        float v = t[tx][i];
        __nv_bfloat16 h = __float2bfloat16(v);
        size_t o = (size_t)(n0 + i) * K + k0 + tx;
        Thi[o] = h;
        Tlo[o] = __float2bfloat16(v - __bfloat162float(h));
    }
}

// ---------------- mma.sync bf16 split GEMM ----------------
// C[M][N] = (Ahi+Alo)[M][K] x ((Bhi+Blo)[N][K])^T via AhBh + AhBl + AlBh.
// 128x128 tile, BK=32, 8 warps (2M x 4N), warp tile 64x32, cp.async 2-stage.
#define MMA_ROWB   80                       // smem bytes per row (32 bf16 + 8 pad)
#define MAT_BYTES  (128*MMA_ROWB)           // 10240
#define STAGE_BYTES (4*MAT_BYTES)           // 40960
#define GEMM_SMEM  (2*STAGE_BYTES)          // 81920

__global__ __launch_bounds__(256) void gemm_mma(const __nv_bfloat16* __restrict__ Ahi,
                                                const __nv_bfloat16* __restrict__ Alo,
                                                const __nv_bfloat16* __restrict__ Bhi,
                                                const __nv_bfloat16* __restrict__ Blo,
                                                float* __restrict__ C, int K, int N)
{
    extern __shared__ __align__(16) char sm[];
    const int tid = threadIdx.x, lane = tid & 31, wid = tid >> 5;
    const int wm = wid >> 2, wn = wid & 3;
    const int m0 = blockIdx.y * 128, n0 = blockIdx.x * 128;
    const uint32_t sbase = smem_u32(sm);
    const size_t rowb = (size_t)K * 2;
    const char* gm[4] = { (const char*)Ahi + (size_t)m0 * rowb,
                          (const char*)Alo + (size_t)m0 * rowb,
                          (const char*)Bhi + (size_t)n0 * rowb,
                          (const char*)Blo + (size_t)n0 * rowb };
    const int NC = K / 32;

    float acc[4][4][4];
#pragma unroll
    for (int i = 0; i < 4; i++)
#pragma unroll
        for (int j = 0; j < 4; j++)
#pragma unroll
            for (int q = 0; q < 4; q++) acc[i][j][q] = 0.f;

    auto pf = [&](int c) {
        const uint32_t st = sbase + (uint32_t)(c & 1) * STAGE_BYTES;
        const int kb = c * 64;  // 32 bf16 = 64 bytes
#pragma unroll
        for (int t = 0; t < 8; t++) {
            int ch = t * 256 + tid;
            int mat = ch >> 9, row = (ch >> 2) & 127, quad = ch & 3;
            cp16(st + mat * MAT_BYTES + row * MMA_ROWB + quad * 16,
                 gm[mat] + (size_t)row * rowb + kb + quad * 16);
        }
        asm volatile("cp.async.commit_group;" ::: "memory");
    };

    pf(0);
    const int lr = lane & 7, lt = lane >> 3;
    const uint32_t lane_off = (uint32_t)(lr + (lt & 1) * 8) * MMA_ROWB + (uint32_t)(lt >> 1) * 16;

    for (int c = 0; c < NC; c++) {
        if (c + 1 < NC) { pf(c + 1); asm volatile("cp.async.wait_group 1;" ::: "memory"); }
        else            {            asm volatile("cp.async.wait_group 0;" ::: "memory"); }
        __syncthreads();
        const uint32_t st = sbase + (uint32_t)(c & 1) * STAGE_BYTES;
#pragma unroll
        for (int ks = 0; ks < 2; ks++) {
            uint32_t ah[4][4], al[4][4], bh[2][4], bl[2][4];
#pragma unroll
            for (int mt = 0; mt < 4; mt++) {
                uint32_t ad = st + (uint32_t)(wm * 64 + mt * 16) * MMA_ROWB + ks * 32 + lane_off;
                ldm_x4(ah[mt][0], ah[mt][1], ah[mt][2], ah[mt][3], ad);
                ldm_x4(al[mt][0], al[mt][1], al[mt][2], al[mt][3], ad + MAT_BYTES);
            }
#pragma unroll
            for (int g = 0; g < 2; g++) {
                uint32_t bd = st + 2 * MAT_BYTES +
                              (uint32_t)(wn * 32 + g * 16) * MMA_ROWB + ks * 32 + lane_off;
                ldm_x4(bh[g][0], bh[g][1], bh[g][2], bh[g][3], bd);
                ldm_x4(bl[g][0], bl[g][1], bl[g][2], bl[g][3], bd + MAT_BYTES);
            }
#pragma unroll
            for (int mt = 0; mt < 4; mt++)
#pragma unroll
                for (int nt = 0; nt < 4; nt++) {
                    const int g = nt >> 1, s = nt & 1;
                    mma_bf16(acc[mt][nt], ah[mt], bh[g][s], bh[g][s + 2]);
                    mma_bf16(acc[mt][nt], ah[mt], bl[g][s], bl[g][s + 2]);
                    mma_bf16(acc[mt][nt], al[mt], bh[g][s], bh[g][s + 2]);
                }
        }
        __syncthreads();
    }

    // epilogue: D frag lane mapping -> (row = lane>>2 [+8], col = (lane&3)*2 [+1])
#pragma unroll
    for (int mt = 0; mt < 4; mt++) {
        const int row = m0 + wm * 64 + mt * 16 + (lane >> 2);
#pragma unroll
        for (int nt = 0; nt < 4; nt++) {
            const int col = n0 + wn * 32 + nt * 8 + (lane & 3) * 2;
            float* p = C + (size_t)row * N + col;
            p[0] = acc[mt][nt][0]; p[1] = acc[mt][nt][1];
            float* q = C + (size_t)(row + 8) * N + col;
            q[0] = acc[mt][nt][2]; q[1] = acc[mt][nt][3];
        }
    }
}

// ---------------- RoPE + layout repack ----------------
__global__ __launch_bounds__(256) void rope_pack(const float* __restrict__ cosb,
                                                 const float* __restrict__ sinb)
{
    int idx = blockIdx.x * 256 + threadIdx.x;
    if (idx < NB * NS * NH * 64) {
        int d = idx & 63, h = (idx >> 6) & 15, s = (idx >> 10) & 2047, b = idx >> 21;
        float c = cosb[s * 64 + d], sn = sinb[s * 64 + d];
        const float* qp = g_Qraw + (size_t)(b * NS + s) * (NH * NHD) + h * NHD;
        float qr = qp[d], qi = qp[64 + d];
        float* qo = g_Q192 + ((size_t)(b * NH + h) * NS + s) * NHEFF;
        qo[d] = qr * (c - sn); qo[64 + d] = qr * (c + sn); qo[128 + d] = qi;
    }
    if (idx < NB * NS * NKVH * 64) {
        int d = idx & 63, kv = (idx >> 6) & 3, s = (idx >> 8) & 2047, b = idx >> 19;
        float c = cosb[s * 64 + d], sn = sinb[s * 64 + d];
        const float* kp = g_Kraw + (size_t)(b * NS + s) * (NKVH * NHD) + kv * NHD;
        float kr = kp[d], ki = kp[64 + d];
        float* ko = g_K192 + ((size_t)(b * NKVH + kv) * NS + s) * NHEFF;
        ko[d] = kr * (c - sn); ko[64 + d] = kr * (c + sn); ko[128 + d] = ki;
    }
    if (idx < NB * NS * NKVH * 128) {
        int d = idx & 127, kv = (idx >> 7) & 3, s = (idx >> 9) & 2047, b = idx >> 20;
        g_Vt[((size_t)(b * NKVH + kv) * NS + s) * NHD + d] =
            g_Vraw[(size_t)(b * NS + s) * (NKVH * NHD) + kv * NHD + d];
    }
}

// ---------------- windowed flash attention (unchanged, known-good) ----------------
#define QK_STR 68
#define V_STR  132
#define SMEM_ATTN_FLOATS (192*QK_STR*2 + 64*V_STR + 64*64)
#define SMEM_ATTN_BYTES  (SMEM_ATTN_FLOATS * 4)

__global__ __launch_bounds__(256) void attn_kernel()
{
    extern __shared__ float smf[];
    float* Qst = smf;
    float* Kst = Qst + 192 * QK_STR;
    float* Vs  = Kst + 192 * QK_STR;
    float* Ps  = Vs + 64 * V_STR;

    const int tid = threadIdx.x;
    const int tx = tid & 15, ty = tid >> 4;
    const int qt = blockIdx.x;
    const int bh = blockIdx.y;
    const int b = bh >> 4, h = bh & 15, kv = h >> 2;
    const int qbase = qt * 64;

    {
        const float* Qg = g_Q192 + ((size_t)(b * NH + h) * NS + qbase) * NHEFF;
#pragma unroll 4
        for (int i = tid; i < 64 * NHEFF; i += 256) {
            int r = i / NHEFF, k = i - r * NHEFF;
            Qst[k * QK_STR + r] = Qg[i];
        }
    }

    float mo[4], l[4], o[4][8];
#pragma unroll
    for (int i = 0; i < 4; i++) {
        mo[i] = -1e30f; l[i] = 0.f;
#pragma unroll
        for (int j = 0; j < 8; j++) o[i][j] = 0.f;
    }

    const int kt0 = (qt > 16) ? (qt - 16) : 0;
    for (int kt = kt0; kt <= qt; kt++) {
        const int kbase = kt * 64;
        const float* Kg = g_K192 + ((size_t)(b * NKVH + kv) * NS + kbase) * NHEFF;
        const float* Vg = g_Vt   + ((size_t)(b * NKVH + kv) * NS + kbase) * NHD;

        __syncthreads();
#pragma unroll 4
        for (int i = tid; i < 64 * NHEFF; i += 256) {
            int r = i / NHEFF, k = i - r * NHEFF;
            Kst[k * QK_STR + r] = Kg[i];
        }
#pragma unroll 2
        for (int i = tid; i < 64 * 32; i += 256) {
            int r = i >> 5, c = (i & 31) * 4;
            *(float4*)&Vs[r * V_STR + c] = *(const float4*)&Vg[r * NHD + c];
        }
        __syncthreads();

        float s4[4][4];
#pragma unroll
        for (int i = 0; i < 4; i++)
#pragma unroll
            for (int j = 0; j < 4; j++) s4[i][j] = 0.f;
#pragma unroll 4
        for (int k = 0; k < NHEFF; k++) {
            float4 av = *(const float4*)&Qst[k * QK_STR + ty * 4];
            float4 bv = *(const float4*)&Kst[k * QK_STR + tx * 4];
            s4[0][0] += av.x * bv.x; s4[0][1] += av.x * bv.y; s4[0][2] += av.x * bv.z; s4[0][3] += av.x * bv.w;
            s4[1][0] += av.y * bv.x; s4[1][1] += av.y * bv.y; s4[1][2] += av.y * bv.z; s4[1][3] += av.y * bv.w;
            s4[2][0] += av.z * bv.x; s4[2][1] += av.z * bv.y; s4[2][2] += av.z * bv.z; s4[2][3] += av.z * bv.w;
            s4[3][0] += av.w * bv.x; s4[3][1] += av.w * bv.y; s4[3][2] += av.w * bv.z; s4[3][3] += av.w * bv.w;
        }

#pragma unroll
        for (int i = 0; i < 4; i++) {
            int q = qbase + ty * 4 + i;
            float rm = -1e30f;
#pragma unroll
            for (int j = 0; j < 4; j++) {
                int kk2 = kbase + tx * 4 + j;
                float sv = (kk2 <= q && kk2 + NWIN > q) ? s4[i][j] * SCALE_F : -1e30f;
                s4[i][j] = sv;
                rm = fmaxf(rm, sv);
            }
            rm = fmaxf(rm, __shfl_xor_sync(0xffffffffu, rm, 8));
            rm = fmaxf(rm, __shfl_xor_sync(0xffffffffu, rm, 4));
            rm = fmaxf(rm, __shfl_xor_sync(0xffffffffu, rm, 2));
            rm = fmaxf(rm, __shfl_xor_sync(0xffffffffu, rm, 1));
            float mn = fmaxf(mo[i], rm);
            float f = __expf(mo[i] - mn);
            mo[i] = mn;
            float rs = 0.f;
#pragma unroll
            for (int j = 0; j < 4; j++) {
                float p = (s4[i][j] > -1e29f) ? __expf(s4[i][j] - mn) : 0.f;
                s4[i][j] = p; rs += p;
            }
            rs += __shfl_xor_sync(0xffffffffu, rs, 8);
            rs += __shfl_xor_sync(0xffffffffu, rs, 4);
            rs += __shfl_xor_sync(0xffffffffu, rs, 2);
            rs += __shfl_xor_sync(0xffffffffu, rs, 1);
            l[i] = l[i] * f + rs;
#pragma unroll
            for (int j = 0; j < 8; j++) o[i][j] *= f;
            *(float4*)&Ps[(ty * 4 + i) * 64 + tx * 4] =
                make_float4(s4[i][0], s4[i][1], s4[i][2], s4[i][3]);
        }
        __syncthreads();

#pragma unroll 2
        for (int k = 0; k < 64; k++) {
            float p0 = Ps[(ty * 4 + 0) * 64 + k];
            float p1 = Ps[(ty * 4 + 1) * 64 + k];
            float p2 = Ps[(ty * 4 + 2) * 64 + k];
            float p3 = Ps[(ty * 4 + 3) * 64 + k];
            float4 v0 = *(const float4*)&Vs[k * V_STR + tx * 4];
            float4 v1 = *(const float4*)&Vs[k * V_STR + 64 + tx * 4];
            o[0][0] += p0 * v0.x; o[0][1] += p0 * v0.y; o[0][2] += p0 * v0.z; o[0][3] += p0 * v0.w;
            o[0][4] += p0 * v1.x; o[0][5] += p0 * v1.y; o[0][6] += p0 * v1.z; o[0][7] += p0 * v1.w;
            o[1][0] += p1 * v0.x; o[1][1] += p1 * v0.y; o[1][2] += p1 * v0.z; o[1][3] += p1 * v0.w;
            o[1][4] += p1 * v1.x; o[1][5] += p1 * v1.y; o[1][6] += p1 * v1.z; o[1][7] += p1 * v1.w;
            o[2][0] += p2 * v0.x; o[2][1] += p2 * v0.y; o[2][2] += p2 * v0.z; o[2][3] += p2 * v0.w;
            o[2][4] += p2 * v1.x; o[2][5] += p2 * v1.y; o[2][6] += p2 * v1.z; o[2][7] += p2 * v1.w;
            o[3][0] += p3 * v0.x; o[3][1] += p3 * v0.y; o[3][2] += p3 * v0.z; o[3][3] += p3 * v0.w;
            o[3][4] += p3 * v1.x; o[3][5] += p3 * v1.y; o[3][6] += p3 * v1.z; o[3][7] += p3 * v1.w;
        }
    }

#pragma unroll
    for (int i = 0; i < 4; i++) {
        int q = qbase + ty * 4 + i;
        float inv = 1.0f / l[i];
        size_t rowbase = (size_t)(b * NS + q) * (NH * NHD) + h * NHD;
        *(float4*)&g_O[rowbase + tx * 4] =
            make_float4(o[i][0] * inv, o[i][1] * inv, o[i][2] * inv, o[i][3] * inv);
        *(float4*)&g_O[rowbase + 64 + tx * 4] =
            make_float4(o[i][4] * inv, o[i][5] * inv, o[i][6] * inv, o[i][7] * inv);
    }
}

// ---------------- launch ----------------
extern "C" void kernel_launch(void* const* d_in, const int* in_sizes, int n_in,
                              void* d_out, int out_size)
{
    (void)in_sizes; (void)n_in; (void)out_size;
    const float* x    = (const float*)d_in[0];
    const float* cosb = (const float*)d_in[1];
    const float* sinb = (const float*)d_in[2];
    const float* wq   = (const float*)d_in[5];
    const float* wk   = (const float*)d_in[6];
    const float* wv   = (const float*)d_in[7];
    const float* wo   = (const float*)d_in[8];
    float* out = (float*)d_out;

    float *Qraw, *Kraw, *Vraw, *O;
    __nv_bfloat16 *xhi, *xlo, *Ohi, *Olo;
    __nv_bfloat16 *wqthi, *wqtlo, *wkthi, *wktlo, *wvthi, *wvtlo, *wothi, *wotlo;
    cudaGetSymbolAddress((void**)&Qraw, g_Qraw);
    cudaGetSymbolAddress((void**)&Kraw, g_Kraw);
    cudaGetSymbolAddress((void**)&Vraw, g_Vraw);
    cudaGetSymbolAddress((void**)&O,    g_O);
    cudaGetSymbolAddress((void**)&xhi,  g_xhi);
    cudaGetSymbolAddress((void**)&xlo,  g_xlo);
    cudaGetSymbolAddress((void**)&Ohi,  g_Ohi);
    cudaGetSymbolAddress((void**)&Olo,  g_Olo);
    cudaGetSymbolAddress((void**)&wqthi, g_wqthi);
    cudaGetSymbolAddress((void**)&wqtlo, g_wqtlo);
    cudaGetSymbolAddress((void**)&wkthi, g_wkthi);
    cudaGetSymbolAddress((void**)&wktlo, g_wktlo);
    cudaGetSymbolAddress((void**)&wvthi, g_wvthi);
    cudaGetSymbolAddress((void**)&wvtlo, g_wvtlo);
    cudaGetSymbolAddress((void**)&wothi, g_wothi);
    cudaGetSymbolAddress((void**)&wotlo, g_wotlo);

    static bool attr_done = false;
    if (!attr_done) {
        cudaFuncSetAttribute(attn_kernel, cudaFuncAttributeMaxDynamicSharedMemorySize,
                             SMEM_ATTN_BYTES);
        cudaFuncSetAttribute(gemm_mma, cudaFuncAttributeMaxDynamicSharedMemorySize,
                             GEMM_SMEM);
        attr_done = true;
    }

    // operand conversion
    cvt_hi_lo<<<(NM * NDIM + 255) / 256, 256>>>(x, xhi, xlo, NM * NDIM);
    cvt_w_t<<<dim3((NH * NHD) / 32, NDIM / 32),  256>>>(wq, wqthi, wqtlo, NDIM, NH * NHD);
    cvt_w_t<<<dim3((NKVH * NHD) / 32, NDIM / 32), 256>>>(wk, wkthi, wktlo, NDIM, NKVH * NHD);
    cvt_w_t<<<dim3((NKVH * NHD) / 32, NDIM / 32), 256>>>(wv, wvthi, wvtlo, NDIM, NKVH * NHD);
    cvt_w_t<<<dim3(NDIM / 32, (NH * NHD) / 32),  256>>>(wo, wothi, wotlo, NH * NHD, NDIM);

    // QKV projections (mma.sync bf16 split)
    gemm_mma<<<dim3((NH * NHD) / 128,   NM / 128), 256, GEMM_SMEM>>>(xhi, xlo, wqthi, wqtlo, Qraw, NDIM, NH * NHD);
    gemm_mma<<<dim3((NKVH * NHD) / 128, NM / 128), 256, GEMM_SMEM>>>(xhi, xlo, wkthi, wktlo, Kraw, NDIM, NKVH * NHD);
    gemm_mma<<<dim3((NKVH * NHD) / 128, NM / 128), 256, GEMM_SMEM>>>(xhi, xlo, wvthi, wvtlo, Vraw, NDIM, NKVH * NHD);

    // RoPE + repack
    rope_pack<<<(NB * NS * NH * 64 + 255) / 256, 256>>>(cosb, sinb);

    // windowed attention
    attn_kernel<<<dim3(NS / 64, NB * NH), 256, SMEM_ATTN_BYTES>>>();

    // output projection
    cvt_hi_lo<<<(NM * NH * NHD + 255) / 256, 256>>>(O, Ohi, Olo, NM * NH * NHD);
    gemm_mma<<<dim3(NDIM / 128, NM / 128), 256, GEMM_SMEM>>>(Ohi, Olo, wothi, wotlo, out, NH * NHD, NDIM);
}

// round 15
// speedup vs baseline: 2.2443x; 1.4947x over previous
#include <cuda_runtime.h>
#include <cuda_bf16.h>
#include <math.h>
#include <stdint.h>

// Problem constants
#define NB    2
#define NS    2048
#define NDIM  2048
#define NH    16
#define NKVH  4
#define NHD   128
#define NHEFF 192
#define NWIN  1024
#define SCALE_F 0.08838834764831845f

#define NM (NB*NS)

// ---------------- scratch ----------------
__device__ float g_Qraw[(size_t)NM * (NH*NHD)];
__device__ float g_Kraw[(size_t)NM * (NKVH*NHD)];
__device__ float g_Vraw[(size_t)NM * (NKVH*NHD)];

// bf16 hi/lo operands
__device__ __nv_bfloat16 g_xhi[(size_t)NM * NDIM];
__device__ __nv_bfloat16 g_xlo[(size_t)NM * NDIM];
__device__ __nv_bfloat16 g_Qhi[(size_t)NB*NH*NS*NHEFF];
__device__ __nv_bfloat16 g_Qlo[(size_t)NB*NH*NS*NHEFF];
__device__ __nv_bfloat16 g_Khi[(size_t)NB*NKVH*NS*NHEFF];
__device__ __nv_bfloat16 g_Klo[(size_t)NB*NKVH*NS*NHEFF];
__device__ __nv_bfloat16 g_Vhi[(size_t)NB*NKVH*NHD*NS];   // transposed [b][kv][d][s]
__device__ __nv_bfloat16 g_Vlo[(size_t)NB*NKVH*NHD*NS];
__device__ __nv_bfloat16 g_Ohi[(size_t)NM * (NH*NHD)];
__device__ __nv_bfloat16 g_Olo[(size_t)NM * (NH*NHD)];
__device__ __nv_bfloat16 g_wqthi[(size_t)(NH*NHD) * NDIM];   // [N][K]
__device__ __nv_bfloat16 g_wqtlo[(size_t)(NH*NHD) * NDIM];
__device__ __nv_bfloat16 g_wkthi[(size_t)(NKVH*NHD) * NDIM];
__device__ __nv_bfloat16 g_wktlo[(size_t)(NKVH*NHD) * NDIM];
__device__ __nv_bfloat16 g_wvthi[(size_t)(NKVH*NHD) * NDIM];
__device__ __nv_bfloat16 g_wvtlo[(size_t)(NKVH*NHD) * NDIM];
__device__ __nv_bfloat16 g_wothi[(size_t)NDIM * (NH*NHD)];
__device__ __nv_bfloat16 g_wotlo[(size_t)NDIM * (NH*NHD)];

// ---------------- portable PTX helpers ----------------
__device__ __forceinline__ uint32_t smem_u32(const void* p) {
    uint32_t a;
    asm("{ .reg .u64 t; cvta.to.shared.u64 t, %1; cvt.u32.u64 %0, t; }" : "=r"(a) : "l"(p));
    return a;
}
__device__ __forceinline__ void cp16(uint32_t dst, const void* src) {
    asm volatile("cp.async.cg.shared.global [%0], [%1], 16;" :: "r"(dst), "l"(src));
}
__device__ __forceinline__ void ldm_x4(uint32_t& r0, uint32_t& r1, uint32_t& r2, uint32_t& r3,
                                       uint32_t addr) {
    asm volatile("ldmatrix.sync.aligned.m8n8.x4.shared.b16 {%0,%1,%2,%3}, [%4];"
                 : "=r"(r0), "=r"(r1), "=r"(r2), "=r"(r3) : "r"(addr));
}
__device__ __forceinline__ void mma_bf16(float* d, const uint32_t* a, uint32_t b0, uint32_t b1) {
    asm volatile(
        "mma.sync.aligned.m16n8k16.row.col.f32.bf16.bf16.f32 "
        "{%0,%1,%2,%3}, {%4,%5,%6,%7}, {%8,%9}, {%0,%1,%2,%3};"
        : "+f"(d[0]), "+f"(d[1]), "+f"(d[2]), "+f"(d[3])
        : "r"(a[0]), "r"(a[1]), "r"(a[2]), "r"(a[3]), "r"(b0), "r"(b1));
}
__device__ __forceinline__ void hl_store(__nv_bfloat16* hi, __nv_bfloat16* lo, size_t i, float v) {
    __nv_bfloat16 h = __float2bfloat16(v);
    hi[i] = h;
    lo[i] = __float2bfloat16(v - __bfloat162float(h));
}
__device__ __forceinline__ void packhl(float x, float y, uint32_t& hi, uint32_t& lo) {
    __nv_bfloat16 hx = __float2bfloat16(x), hy = __float2bfloat16(y);
    float rx = x - __bfloat162float(hx), ry = y - __bfloat162float(hy);
    __nv_bfloat16 lx = __float2bfloat16(rx), ly = __float2bfloat16(ry);
    hi = ((uint32_t)__bfloat16_as_ushort(hy) << 16) | __bfloat16_as_ushort(hx);
    lo = ((uint32_t)__bfloat16_as_ushort(ly) << 16) | __bfloat16_as_ushort(lx);
}

// ---------------- conversion kernels ----------------
__global__ __launch_bounds__(256) void cvt_hi_lo(const float* __restrict__ in,
                                                 __nv_bfloat16* __restrict__ hi,
                                                 __nv_bfloat16* __restrict__ lo, int n)
{
    int i = blockIdx.x * 256 + threadIdx.x;
    if (i < n) {
        float v = in[i];
        __nv_bfloat16 h = __float2bfloat16(v);
        hi[i] = h;
        lo[i] = __float2bfloat16(v - __bfloat162float(h));
    }
}

__global__ __launch_bounds__(256) void cvt_w_t(const float* __restrict__ W,
                                               __nv_bfloat16* __restrict__ Thi,
                                               __nv_bfloat16* __restrict__ Tlo,
                                               int K, int N)
{
    __shared__ float t[32][33];
    int n0 = blockIdx.x * 32, k0 = blockIdx.y * 32;
    int tx = threadIdx.x & 31, ty = threadIdx.x >> 5;
#pragma unroll
    for (int i = ty; i < 32; i += 8)
        t[i][tx] = W[(size_t)(k0 + i) * N + n0 + tx];
    __syncthreads();
#pragma unroll
    for (int i = ty; i < 32; i += 8) {
        float v = t[tx][i];
        __nv_bfloat16 h = __float2bfloat16(v);
        size_t o = (size_t)(n0 + i) * K + k0 + tx;
        Thi[o] = h;
        Tlo[o] = __float2bfloat16(v - __bfloat162float(h));
    }
}

// ---------------- mma.sync bf16 split GEMM ----------------
#define MMA_ROWB   80
#define MAT_BYTES  (128*MMA_ROWB)
#define STAGE_BYTES (4*MAT_BYTES)
#define GEMM_SMEM  (2*STAGE_BYTES)

__global__ __launch_bounds__(256) void gemm_mma(const __nv_bfloat16* __restrict__ Ahi,
                                                const __nv_bfloat16* __restrict__ Alo,
                                                const __nv_bfloat16* __restrict__ Bhi,
                                                const __nv_bfloat16* __restrict__ Blo,
                                                float* __restrict__ C, int K, int N)
{
    extern __shared__ __align__(16) char sm[];
    const int tid = threadIdx.x, lane = tid & 31, wid = tid >> 5;
    const int wm = wid >> 2, wn = wid & 3;
    const int m0 = blockIdx.y * 128, n0 = blockIdx.x * 128;
    const uint32_t sbase = smem_u32(sm);
    const size_t rowb = (size_t)K * 2;
    const char* gm[4] = { (const char*)Ahi + (size_t)m0 * rowb,
                          (const char*)Alo + (size_t)m0 * rowb,
                          (const char*)Bhi + (size_t)n0 * rowb,
                          (const char*)Blo + (size_t)n0 * rowb };
    const int NC = K / 32;

    float acc[4][4][4];
#pragma unroll
    for (int i = 0; i < 4; i++)
#pragma unroll
        for (int j = 0; j < 4; j++)
#pragma unroll
            for (int q = 0; q < 4; q++) acc[i][j][q] = 0.f;

    auto pf = [&](int c) {
        const uint32_t st = sbase + (uint32_t)(c & 1) * STAGE_BYTES;
        const int kb = c * 64;
#pragma unroll
        for (int t = 0; t < 8; t++) {
            int ch = t * 256 + tid;
            int mat = ch >> 9, row = (ch >> 2) & 127, quad = ch & 3;
            cp16(st + mat * MAT_BYTES + row * MMA_ROWB + quad * 16,
                 gm[mat] + (size_t)row * rowb + kb + quad * 16);
        }
        asm volatile("cp.async.commit_group;" ::: "memory");
    };

    pf(0);
    const int lr = lane & 7, lt = lane >> 3;
    const uint32_t lane_off = (uint32_t)(lr + (lt & 1) * 8) * MMA_ROWB + (uint32_t)(lt >> 1) * 16;

    for (int c = 0; c < NC; c++) {
        if (c + 1 < NC) { pf(c + 1); asm volatile("cp.async.wait_group 1;" ::: "memory"); }
        else            {            asm volatile("cp.async.wait_group 0;" ::: "memory"); }
        __syncthreads();
        const uint32_t st = sbase + (uint32_t)(c & 1) * STAGE_BYTES;
#pragma unroll
        for (int ks = 0; ks < 2; ks++) {
            uint32_t ah[4][4], al[4][4], bh[2][4], bl[2][4];
#pragma unroll
            for (int mt = 0; mt < 4; mt++) {
                uint32_t ad = st + (uint32_t)(wm * 64 + mt * 16) * MMA_ROWB + ks * 32 + lane_off;
                ldm_x4(ah[mt][0], ah[mt][1], ah[mt][2], ah[mt][3], ad);
                ldm_x4(al[mt][0], al[mt][1], al[mt][2], al[mt][3], ad + MAT_BYTES);
            }
#pragma unroll
            for (int g = 0; g < 2; g++) {
                uint32_t bd = st + 2 * MAT_BYTES +
                              (uint32_t)(wn * 32 + g * 16) * MMA_ROWB + ks * 32 + lane_off;
                ldm_x4(bh[g][0], bh[g][1], bh[g][2], bh[g][3], bd);
                ldm_x4(bl[g][0], bl[g][1], bl[g][2], bl[g][3], bd + MAT_BYTES);
            }
#pragma unroll
            for (int mt = 0; mt < 4; mt++)
#pragma unroll
                for (int nt = 0; nt < 4; nt++) {
                    const int g = nt >> 1, s = nt & 1;
                    mma_bf16(acc[mt][nt], ah[mt], bh[g][s], bh[g][s + 2]);
                    mma_bf16(acc[mt][nt], ah[mt], bl[g][s], bl[g][s + 2]);
                    mma_bf16(acc[mt][nt], al[mt], bh[g][s], bh[g][s + 2]);
                }
        }
        __syncthreads();
    }

#pragma unroll
    for (int mt = 0; mt < 4; mt++) {
        const int row = m0 + wm * 64 + mt * 16 + (lane >> 2);
#pragma unroll
        for (int nt = 0; nt < 4; nt++) {
            const int col = n0 + wn * 32 + nt * 8 + (lane & 3) * 2;
            float* p = C + (size_t)row * N + col;
            p[0] = acc[mt][nt][0]; p[1] = acc[mt][nt][1];
            float* q = C + (size_t)(row + 8) * N + col;
            q[0] = acc[mt][nt][2]; q[1] = acc[mt][nt][3];
        }
    }
}

// ---------------- RoPE + hi/lo pack ----------------
__global__ __launch_bounds__(256) void rope_pack(const float* __restrict__ cosb,
                                                 const float* __restrict__ sinb)
{
    int idx = blockIdx.x * 256 + threadIdx.x;
    if (idx < NB * NS * NH * 64) {
        int d = idx & 63, h = (idx >> 6) & 15, s = (idx >> 10) & 2047, b = idx >> 21;
        float c = cosb[s * 64 + d], sn = sinb[s * 64 + d];
        const float* qp = g_Qraw + (size_t)(b * NS + s) * (NH * NHD) + h * NHD;
        float qr = qp[d], qi = qp[64 + d];
        size_t base = ((size_t)(b * NH + h) * NS + s) * NHEFF;
        hl_store(g_Qhi, g_Qlo, base + d,       qr * (c - sn));
        hl_store(g_Qhi, g_Qlo, base + 64 + d,  qr * (c + sn));
        hl_store(g_Qhi, g_Qlo, base + 128 + d, qi);
    }
    if (idx < NB * NS * NKVH * 64) {
        int d = idx & 63, kv = (idx >> 6) & 3, s = (idx >> 8) & 2047, b = idx >> 19;
        float c = cosb[s * 64 + d], sn = sinb[s * 64 + d];
        const float* kp = g_Kraw + (size_t)(b * NS + s) * (NKVH * NHD) + kv * NHD;
        float kr = kp[d], ki = kp[64 + d];
        size_t base = ((size_t)(b * NKVH + kv) * NS + s) * NHEFF;
        hl_store(g_Khi, g_Klo, base + d,       kr * (c - sn));
        hl_store(g_Khi, g_Klo, base + 64 + d,  kr * (c + sn));
        hl_store(g_Khi, g_Klo, base + 128 + d, ki);
    }
    if (idx < NB * NS * NKVH * 128) {
        int d = idx & 127, kv = (idx >> 7) & 3, s = (idx >> 9) & 2047, b = idx >> 20;
        float v = g_Vraw[(size_t)(b * NS + s) * (NKVH * NHD) + kv * NHD + d];
        size_t di = ((size_t)(b * NKVH + kv) * NHD + d) * NS + s;   // transposed [d][s]
        hl_store(g_Vhi, g_Vlo, di, v);
    }
}

// ---------------- tensor-core windowed flash attention ----------------
// CTA: 64 q-rows x one (b,h). 4 warps x 16 q-rows. K-tiles of 64, cp.async double-buffered.
#define AQ_ROWB 400                          // Q/K smem row bytes (192 bf16 + pad)
#define AV_ROWB 144                          // V smem row bytes (64 bf16 + pad)
#define AKT_B   (64*AQ_ROWB)                 // 25600 per K matrix
#define AVT_B   (128*AV_ROWB)                // 18432 per V matrix
#define ASTG_B  (2*AKT_B + 2*AVT_B)          // 88064 per stage (Khi,Klo,Vhi,Vlo)
#define AQ_OFF  (2*ASTG_B)                   // 176128
#define ATTN_SMEM (AQ_OFF + 2*AKT_B)         // 227328

__global__ __launch_bounds__(128) void attn_mma()
{
    extern __shared__ __align__(16) char sm[];
    const uint32_t sb = smem_u32(sm);
    const int tid = threadIdx.x, lane = tid & 31, wq = tid >> 5;
    const int qt = blockIdx.x, bh = blockIdx.y;
    const int b = bh >> 4, h = bh & 15, kv = h >> 2;
    const int qbase = qt * 64;

    const __nv_bfloat16* Qh = g_Qhi + ((size_t)(b * NH + h) * NS + qbase) * NHEFF;
    const __nv_bfloat16* Ql = g_Qlo + ((size_t)(b * NH + h) * NS + qbase) * NHEFF;
    const __nv_bfloat16* Kh = g_Khi + (size_t)(b * NKVH + kv) * NS * NHEFF;
    const __nv_bfloat16* Kl = g_Klo + (size_t)(b * NKVH + kv) * NS * NHEFF;
    const __nv_bfloat16* Vh = g_Vhi + (size_t)(b * NKVH + kv) * NHD * NS;
    const __nv_bfloat16* Vl = g_Vlo + (size_t)(b * NKVH + kv) * NHD * NS;

    // Q tile load (joins first commit group)
    for (int i = tid; i < 3072; i += 128) {
        int m = i >= 1536, idx = i - m * 1536;
        int row = idx / 24, c = idx - row * 24;
        cp16(sb + AQ_OFF + m * AKT_B + row * AQ_ROWB + c * 16,
             (m ? Ql : Qh) + (size_t)row * NHEFF + c * 8);
    }

    auto pf = [&](int kt, int buf) {
        const uint32_t st = sb + buf * ASTG_B;
        const int kb = kt * 64;
        for (int i = tid; i < 3072; i += 128) {
            int m = i >= 1536, idx = i - m * 1536;
            int row = idx / 24, c = idx - row * 24;
            cp16(st + m * AKT_B + row * AQ_ROWB + c * 16,
                 (m ? Kl : Kh) + (size_t)(kb + row) * NHEFF + c * 8);
        }
        for (int i = tid; i < 2048; i += 128) {
            int m = i >= 1024, idx = i & 1023;
            int row = idx >> 3, c = idx & 7;
            cp16(st + 2 * AKT_B + m * AVT_B + row * AV_ROWB + c * 16,
                 (m ? Vl : Vh) + (size_t)row * NS + kb + c * 8);
        }
        asm volatile("cp.async.commit_group;" ::: "memory");
    };

    const int kt0 = (qt > 16) ? (qt - 16) : 0;
    pf(kt0, 0);
    if (kt0 < qt) pf(kt0 + 1, 1);

    const int rowsel = (lane & 7) + ((lane >> 3) & 1) * 8;
    const uint32_t laQ = (uint32_t)rowsel * AQ_ROWB + (uint32_t)(lane >> 4) * 16;
    const uint32_t laV = (uint32_t)rowsel * AV_ROWB + (uint32_t)(lane >> 4) * 16;
    const uint32_t qa = sb + AQ_OFF + (uint32_t)(wq * 16) * AQ_ROWB + laQ;

    const int q0 = qbase + wq * 16 + (lane >> 2);
    const int q1 = q0 + 8;

    float mo0 = -1e30f, mo1 = -1e30f, l0 = 0.f, l1 = 0.f;
    float oacc[16][4];
#pragma unroll
    for (int i = 0; i < 16; i++)
#pragma unroll
        for (int j = 0; j < 4; j++) oacc[i][j] = 0.f;

    for (int kt = kt0; kt <= qt; kt++) {
        const int buf = (kt - kt0) & 1;
        if (kt < qt) asm volatile("cp.async.wait_group 1;" ::: "memory");
        else         asm volatile("cp.async.wait_group 0;" ::: "memory");
        __syncthreads();
        const uint32_t stK = sb + buf * ASTG_B;
        const uint32_t stV = stK + 2 * AKT_B;
        const int kbase = kt * 64;

        // ---- S = Q K^T (3-term split) ----
        float sacc[8][4];
#pragma unroll
        for (int i = 0; i < 8; i++)
#pragma unroll
            for (int j = 0; j < 4; j++) sacc[i][j] = 0.f;

#pragma unroll 3
        for (int ks = 0; ks < 12; ks++) {
            uint32_t ah[4], al[4];
            ldm_x4(ah[0], ah[1], ah[2], ah[3], qa + ks * 32);
            ldm_x4(al[0], al[1], al[2], al[3], qa + AKT_B + ks * 32);
#pragma unroll
            for (int g = 0; g < 4; g++) {
                uint32_t bh4[4], bl4[4];
                uint32_t bd = stK + (uint32_t)(g * 16) * AQ_ROWB + laQ + ks * 32;
                ldm_x4(bh4[0], bh4[1], bh4[2], bh4[3], bd);
                ldm_x4(bl4[0], bl4[1], bl4[2], bl4[3], bd + AKT_B);
                mma_bf16(sacc[2 * g],     ah, bh4[0], bh4[2]);
                mma_bf16(sacc[2 * g],     ah, bl4[0], bl4[2]);
                mma_bf16(sacc[2 * g],     al, bh4[0], bh4[2]);
                mma_bf16(sacc[2 * g + 1], ah, bh4[1], bh4[3]);
                mma_bf16(sacc[2 * g + 1], ah, bl4[1], bl4[3]);
                mma_bf16(sacc[2 * g + 1], al, bh4[1], bh4[3]);
            }
        }

        // ---- masked online softmax ----
        float rm0 = -1e30f, rm1 = -1e30f;
#pragma unroll
        for (int j = 0; j < 8; j++) {
            int cb = kbase + j * 8 + (lane & 3) * 2;
#pragma unroll
            for (int e = 0; e < 2; e++) {
                int c = cb + e;
                float v = sacc[j][e] * SCALE_F;
                v = (c <= q0 && c + NWIN > q0) ? v : -1e30f;
                sacc[j][e] = v; rm0 = fmaxf(rm0, v);
                float w = sacc[j][e + 2] * SCALE_F;
                w = (c <= q1 && c + NWIN > q1) ? w : -1e30f;
                sacc[j][e + 2] = w; rm1 = fmaxf(rm1, w);
            }
        }
        rm0 = fmaxf(rm0, __shfl_xor_sync(0xffffffffu, rm0, 1));
        rm0 = fmaxf(rm0, __shfl_xor_sync(0xffffffffu, rm0, 2));
        rm1 = fmaxf(rm1, __shfl_xor_sync(0xffffffffu, rm1, 1));
        rm1 = fmaxf(rm1, __shfl_xor_sync(0xffffffffu, rm1, 2));
        float mn0 = fmaxf(mo0, rm0), f0 = __expf(mo0 - mn0); mo0 = mn0;
        float mn1 = fmaxf(mo1, rm1), f1 = __expf(mo1 - mn1); mo1 = mn1;
        float rs0 = 0.f, rs1 = 0.f;
#pragma unroll
        for (int j = 0; j < 8; j++) {
#pragma unroll
            for (int e = 0; e < 2; e++) {
                float p = (sacc[j][e] > -1e29f) ? __expf(sacc[j][e] - mn0) : 0.f;
                sacc[j][e] = p; rs0 += p;
                float r = (sacc[j][e + 2] > -1e29f) ? __expf(sacc[j][e + 2] - mn1) : 0.f;
                sacc[j][e + 2] = r; rs1 += r;
            }
        }
        rs0 += __shfl_xor_sync(0xffffffffu, rs0, 1);
        rs0 += __shfl_xor_sync(0xffffffffu, rs0, 2);
        rs1 += __shfl_xor_sync(0xffffffffu, rs1, 1);
        rs1 += __shfl_xor_sync(0xffffffffu, rs1, 2);
        l0 = l0 * f0 + rs0;
        l1 = l1 * f1 + rs1;
#pragma unroll
        for (int nt = 0; nt < 16; nt++) {
            oacc[nt][0] *= f0; oacc[nt][1] *= f0;
            oacc[nt][2] *= f1; oacc[nt][3] *= f1;
        }

        // ---- O += P V (3-term split, P from registers) ----
#pragma unroll
        for (int ks = 0; ks < 4; ks++) {
            uint32_t ph[4], pl[4];
            packhl(sacc[2 * ks][0],     sacc[2 * ks][1],     ph[0], pl[0]);
            packhl(sacc[2 * ks][2],     sacc[2 * ks][3],     ph[1], pl[1]);
            packhl(sacc[2 * ks + 1][0], sacc[2 * ks + 1][1], ph[2], pl[2]);
            packhl(sacc[2 * ks + 1][2], sacc[2 * ks + 1][3], ph[3], pl[3]);
#pragma unroll
            for (int g = 0; g < 8; g++) {
                uint32_t vh4[4], vl4[4];
                uint32_t vd = stV + (uint32_t)(g * 16) * AV_ROWB + laV + ks * 32;
                ldm_x4(vh4[0], vh4[1], vh4[2], vh4[3], vd);
                ldm_x4(vl4[0], vl4[1], vl4[2], vl4[3], vd + AVT_B);
                mma_bf16(oacc[2 * g],     ph, vh4[0], vh4[2]);
                mma_bf16(oacc[2 * g],     ph, vl4[0], vl4[2]);
                mma_bf16(oacc[2 * g],     pl, vh4[0], vh4[2]);
                mma_bf16(oacc[2 * g + 1], ph, vh4[1], vh4[3]);
                mma_bf16(oacc[2 * g + 1], ph, vl4[1], vl4[3]);
                mma_bf16(oacc[2 * g + 1], pl, vh4[1], vh4[3]);
            }
        }
        __syncthreads();
        if (kt + 2 <= qt) pf(kt + 2, buf);
    }

    // ---- epilogue: normalize, split hi/lo, write O (b,s,h,d) ----
    const float i0 = 1.f / l0, i1 = 1.f / l1;
    const size_t ro0 = (size_t)(b * NS + q0) * (NH * NHD) + h * NHD;
    const size_t ro1 = ro0 + (size_t)8 * (NH * NHD);
#pragma unroll
    for (int nt = 0; nt < 16; nt++) {
        const int col = nt * 8 + (lane & 3) * 2;
        uint32_t hi, lo;
        packhl(oacc[nt][0] * i0, oacc[nt][1] * i0, hi, lo);
        *(uint32_t*)&g_Ohi[ro0 + col] = hi;
        *(uint32_t*)&g_Olo[ro0 + col] = lo;
        packhl(oacc[nt][2] * i1, oacc[nt][3] * i1, hi, lo);
        *(uint32_t*)&g_Ohi[ro1 + col] = hi;
        *(uint32_t*)&g_Olo[ro1 + col] = lo;
    }
}

// ---------------- launch ----------------
extern "C" void kernel_launch(void* const* d_in, const int* in_sizes, int n_in,
                              void* d_out, int out_size)
{
    (void)in_sizes; (void)n_in; (void)out_size;
    const float* x    = (const float*)d_in[0];
    const float* cosb = (const float*)d_in[1];
    const float* sinb = (const float*)d_in[2];
    const float* wq   = (const float*)d_in[5];
    const float* wk   = (const float*)d_in[6];
    const float* wv   = (const float*)d_in[7];
    const float* wo   = (const float*)d_in[8];
    float* out = (float*)d_out;

    float *Qraw, *Kraw, *Vraw;
    __nv_bfloat16 *xhi, *xlo, *Ohi, *Olo;
    __nv_bfloat16 *wqthi, *wqtlo, *wkthi, *wktlo, *wvthi, *wvtlo, *wothi, *wotlo;
    cudaGetSymbolAddress((void**)&Qraw, g_Qraw);
    cudaGetSymbolAddress((void**)&Kraw, g_Kraw);
    cudaGetSymbolAddress((void**)&Vraw, g_Vraw);
    cudaGetSymbolAddress((void**)&xhi,  g_xhi);
    cudaGetSymbolAddress((void**)&xlo,  g_xlo);
    cudaGetSymbolAddress((void**)&Ohi,  g_Ohi);
    cudaGetSymbolAddress((void**)&Olo,  g_Olo);
    cudaGetSymbolAddress((void**)&wqthi, g_wqthi);
    cudaGetSymbolAddress((void**)&wqtlo, g_wqtlo);
    cudaGetSymbolAddress((void**)&wkthi, g_wkthi);
    cudaGetSymbolAddress((void**)&wktlo, g_wktlo);
    cudaGetSymbolAddress((void**)&wvthi, g_wvthi);
    cudaGetSymbolAddress((void**)&wvtlo, g_wvtlo);
    cudaGetSymbolAddress((void**)&wothi, g_wothi);
    cudaGetSymbolAddress((void**)&wotlo, g_wotlo);

    static bool attr_done = false;
    if (!attr_done) {
        cudaFuncSetAttribute(gemm_mma, cudaFuncAttributeMaxDynamicSharedMemorySize, GEMM_SMEM);
        cudaFuncSetAttribute(attn_mma, cudaFuncAttributeMaxDynamicSharedMemorySize, ATTN_SMEM);
        attr_done = true;
    }

    // operand conversion
    cvt_hi_lo<<<(NM * NDIM + 255) / 256, 256>>>(x, xhi, xlo, NM * NDIM);
    cvt_w_t<<<dim3((NH * NHD) / 32, NDIM / 32),  256>>>(wq, wqthi, wqtlo, NDIM, NH * NHD);
    cvt_w_t<<<dim3((NKVH * NHD) / 32, NDIM / 32), 256>>>(wk, wkthi, wktlo, NDIM, NKVH * NHD);
    cvt_w_t<<<dim3((NKVH * NHD) / 32, NDIM / 32), 256>>>(wv, wvthi, wvtlo, NDIM, NKVH * NHD);
    cvt_w_t<<<dim3(NDIM / 32, (NH * NHD) / 32),  256>>>(wo, wothi, wotlo, NH * NHD, NDIM);

    // QKV projections
    gemm_mma<<<dim3((NH * NHD) / 128,   NM / 128), 256, GEMM_SMEM>>>(xhi, xlo, wqthi, wqtlo, Qraw, NDIM, NH * NHD);
    gemm_mma<<<dim3((NKVH * NHD) / 128, NM / 128), 256, GEMM_SMEM>>>(xhi, xlo, wkthi, wktlo, Kraw, NDIM, NKVH * NHD);
    gemm_mma<<<dim3((NKVH * NHD) / 128, NM / 128), 256, GEMM_SMEM>>>(xhi, xlo, wvthi, wvtlo, Vraw, NDIM, NKVH * NHD);

    // RoPE + hi/lo pack
    rope_pack<<<(NB * NS * NH * 64 + 255) / 256, 256>>>(cosb, sinb);

    // tensor-core windowed attention (writes Ohi/Olo directly)
    attn_mma<<<dim3(NS / 64, NB * NH), 128, ATTN_SMEM>>>();

    // output projection
    gemm_mma<<<dim3(NDIM / 128, NM / 128), 256, GEMM_SMEM>>>(Ohi, Olo, wothi, wotlo, out, NH * NHD, NDIM);
}

// round 16
// speedup vs baseline: 2.2961x; 1.0231x over previous
#include <cuda_runtime.h>
#include <cuda_bf16.h>
#include <math.h>
#include <stdint.h>

// Problem constants
#define NB    2
#define NS    2048
#define NDIM  2048
#define NH    16
#define NKVH  4
#define NHD   128
#define NHEFF 192
#define NWIN  1024
#define SCALE_F 0.08838834764831845f

#define NM (NB*NS)

// ---------------- scratch ----------------
__device__ float g_Qraw[(size_t)NM * (NH*NHD)];
__device__ float g_Kraw[(size_t)NM * (NKVH*NHD)];
__device__ float g_Vraw[(size_t)NM * (NKVH*NHD)];

// bf16 hi/lo operands
__device__ __nv_bfloat16 g_xhi[(size_t)NM * NDIM];
__device__ __nv_bfloat16 g_xlo[(size_t)NM * NDIM];
__device__ __nv_bfloat16 g_Qhi[(size_t)NB*NH*NS*NHEFF];
__device__ __nv_bfloat16 g_Qlo[(size_t)NB*NH*NS*NHEFF];
__device__ __nv_bfloat16 g_Khi[(size_t)NB*NKVH*NS*NHEFF];
__device__ __nv_bfloat16 g_Klo[(size_t)NB*NKVH*NS*NHEFF];
__device__ __nv_bfloat16 g_Vhi[(size_t)NB*NKVH*NHD*NS];   // transposed [b][kv][d][s]
__device__ __nv_bfloat16 g_Vlo[(size_t)NB*NKVH*NHD*NS];
__device__ __nv_bfloat16 g_Ohi[(size_t)NM * (NH*NHD)];
__device__ __nv_bfloat16 g_Olo[(size_t)NM * (NH*NHD)];
__device__ __nv_bfloat16 g_wqthi[(size_t)(NH*NHD) * NDIM];   // [N][K]
__device__ __nv_bfloat16 g_wqtlo[(size_t)(NH*NHD) * NDIM];
__device__ __nv_bfloat16 g_wkthi[(size_t)(NKVH*NHD) * NDIM];
__device__ __nv_bfloat16 g_wktlo[(size_t)(NKVH*NHD) * NDIM];
__device__ __nv_bfloat16 g_wvthi[(size_t)(NKVH*NHD) * NDIM];
__device__ __nv_bfloat16 g_wvtlo[(size_t)(NKVH*NHD) * NDIM];
__device__ __nv_bfloat16 g_wothi[(size_t)NDIM * (NH*NHD)];
__device__ __nv_bfloat16 g_wotlo[(size_t)NDIM * (NH*NHD)];

// ---------------- portable PTX helpers ----------------
__device__ __forceinline__ uint32_t smem_u32(const void* p) {
    uint32_t a;
    asm("{ .reg .u64 t; cvta.to.shared.u64 t, %1; cvt.u32.u64 %0, t; }" : "=r"(a) : "l"(p));
    return a;
}
__device__ __forceinline__ void cp16(uint32_t dst, const void* src) {
    asm volatile("cp.async.cg.shared.global [%0], [%1], 16;" :: "r"(dst), "l"(src));
}
__device__ __forceinline__ void ldm_x4(uint32_t& r0, uint32_t& r1, uint32_t& r2, uint32_t& r3,
                                       uint32_t addr) {
    asm volatile("ldmatrix.sync.aligned.m8n8.x4.shared.b16 {%0,%1,%2,%3}, [%4];"
                 : "=r"(r0), "=r"(r1), "=r"(r2), "=r"(r3) : "r"(addr));
}
__device__ __forceinline__ void mma_bf16(float* d, const uint32_t* a, uint32_t b0, uint32_t b1) {
    asm volatile(
        "mma.sync.aligned.m16n8k16.row.col.f32.bf16.bf16.f32 "
        "{%0,%1,%2,%3}, {%4,%5,%6,%7}, {%8,%9}, {%0,%1,%2,%3};"
        : "+f"(d[0]), "+f"(d[1]), "+f"(d[2]), "+f"(d[3])
        : "r"(a[0]), "r"(a[1]), "r"(a[2]), "r"(a[3]), "r"(b0), "r"(b1));
}
__device__ __forceinline__ void hl_store(__nv_bfloat16* hi, __nv_bfloat16* lo, size_t i, float v) {
    __nv_bfloat16 h = __float2bfloat16(v);
    hi[i] = h;
    lo[i] = __float2bfloat16(v - __bfloat162float(h));
}
__device__ __forceinline__ void packhl(float x, float y, uint32_t& hi, uint32_t& lo) {
    __nv_bfloat16 hx = __float2bfloat16(x), hy = __float2bfloat16(y);
    float rx = x - __bfloat162float(hx), ry = y - __bfloat162float(hy);
    __nv_bfloat16 lx = __float2bfloat16(rx), ly = __float2bfloat16(ry);
    hi = ((uint32_t)__bfloat16_as_ushort(hy) << 16) | __bfloat16_as_ushort(hx);
    lo = ((uint32_t)__bfloat16_as_ushort(ly) << 16) | __bfloat16_as_ushort(lx);
}

// ---------------- conversion kernels ----------------
__global__ __launch_bounds__(256) void cvt_hi_lo(const float* __restrict__ in,
                                                 __nv_bfloat16* __restrict__ hi,
                                                 __nv_bfloat16* __restrict__ lo, int n)
{
    int i = blockIdx.x * 256 + threadIdx.x;
    if (i < n) {
        float v = in[i];
        __nv_bfloat16 h = __float2bfloat16(v);
        hi[i] = h;
        lo[i] = __float2bfloat16(v - __bfloat162float(h));
    }
}

__global__ __launch_bounds__(256) void cvt_w_t(const float* __restrict__ W,
                                               __nv_bfloat16* __restrict__ Thi,
                                               __nv_bfloat16* __restrict__ Tlo,
                                               int K, int N)
{
    __shared__ float t[32][33];
    int n0 = blockIdx.x * 32, k0 = blockIdx.y * 32;
    int tx = threadIdx.x & 31, ty = threadIdx.x >> 5;
#pragma unroll
    for (int i = ty; i < 32; i += 8)
        t[i][tx] = W[(size_t)(k0 + i) * N + n0 + tx];
    __syncthreads();
#pragma unroll
    for (int i = ty; i < 32; i += 8) {
        float v = t[tx][i];
        __nv_bfloat16 h = __float2bfloat16(v);
        size_t o = (size_t)(n0 + i) * K + k0 + tx;
        Thi[o] = h;
        Tlo[o] = __float2bfloat16(v - __bfloat162float(h));
    }
}

// ---------------- mma.sync bf16 split GEMM (BK=64, 2-stage) ----------------
#define MMA_ROWB   144                      // 128 data bytes (64 bf16) + 16 pad
#define MAT_BYTES  (128*MMA_ROWB)           // 18432
#define STAGE_BYTES (4*MAT_BYTES)           // 73728
#define GEMM_SMEM  (2*STAGE_BYTES)          // 147456

__global__ __launch_bounds__(256) void gemm_mma(const __nv_bfloat16* __restrict__ Ahi,
                                                const __nv_bfloat16* __restrict__ Alo,
                                                const __nv_bfloat16* __restrict__ Bhi,
                                                const __nv_bfloat16* __restrict__ Blo,
                                                float* __restrict__ C, int K, int N)
{
    extern __shared__ __align__(16) char sm[];
    const int tid = threadIdx.x, lane = tid & 31, wid = tid >> 5;
    const int wm = wid >> 2, wn = wid & 3;
    const int m0 = blockIdx.y * 128, n0 = blockIdx.x * 128;
    const uint32_t sbase = smem_u32(sm);
    const size_t rowb = (size_t)K * 2;
    const char* gm[4] = { (const char*)Ahi + (size_t)m0 * rowb,
                          (const char*)Alo + (size_t)m0 * rowb,
                          (const char*)Bhi + (size_t)n0 * rowb,
                          (const char*)Blo + (size_t)n0 * rowb };
    const int NC = K / 64;

    float acc[4][4][4];
#pragma unroll
    for (int i = 0; i < 4; i++)
#pragma unroll
        for (int j = 0; j < 4; j++)
#pragma unroll
            for (int q = 0; q < 4; q++) acc[i][j][q] = 0.f;

    auto pf = [&](int c) {
        const uint32_t st = sbase + (uint32_t)(c & 1) * STAGE_BYTES;
        const int kb = c * 128;  // 64 bf16 = 128 bytes
#pragma unroll
        for (int t = 0; t < 16; t++) {
            int ch = t * 256 + tid;
            int mat = ch >> 10, row = (ch >> 3) & 127, quad = ch & 7;
            cp16(st + mat * MAT_BYTES + row * MMA_ROWB + quad * 16,
                 gm[mat] + (size_t)row * rowb + kb + quad * 16);
        }
        asm volatile("cp.async.commit_group;" ::: "memory");
    };

    pf(0);
    const int lr = lane & 7, lt = lane >> 3;
    const uint32_t lane_off = (uint32_t)(lr + (lt & 1) * 8) * MMA_ROWB + (uint32_t)(lt >> 1) * 16;

    for (int c = 0; c < NC; c++) {
        if (c + 1 < NC) { pf(c + 1); asm volatile("cp.async.wait_group 1;" ::: "memory"); }
        else            {            asm volatile("cp.async.wait_group 0;" ::: "memory"); }
        __syncthreads();
        const uint32_t st = sbase + (uint32_t)(c & 1) * STAGE_BYTES;
#pragma unroll
        for (int ks = 0; ks < 4; ks++) {
            uint32_t ah[4][4], al[4][4], bh[2][4], bl[2][4];
#pragma unroll
            for (int mt = 0; mt < 4; mt++) {
                uint32_t ad = st + (uint32_t)(wm * 64 + mt * 16) * MMA_ROWB + ks * 32 + lane_off;
                ldm_x4(ah[mt][0], ah[mt][1], ah[mt][2], ah[mt][3], ad);
                ldm_x4(al[mt][0], al[mt][1], al[mt][2], al[mt][3], ad + MAT_BYTES);
            }
#pragma unroll
            for (int g = 0; g < 2; g++) {
                uint32_t bd = st + 2 * MAT_BYTES +
                              (uint32_t)(wn * 32 + g * 16) * MMA_ROWB + ks * 32 + lane_off;
                ldm_x4(bh[g][0], bh[g][1], bh[g][2], bh[g][3], bd);
                ldm_x4(bl[g][0], bl[g][1], bl[g][2], bl[g][3], bd + MAT_BYTES);
            }
#pragma unroll
            for (int mt = 0; mt < 4; mt++)
#pragma unroll
                for (int nt = 0; nt < 4; nt++) {
                    const int g = nt >> 1, s = nt & 1;
                    mma_bf16(acc[mt][nt], ah[mt], bh[g][s], bh[g][s + 2]);
                    mma_bf16(acc[mt][nt], ah[mt], bl[g][s], bl[g][s + 2]);
                    mma_bf16(acc[mt][nt], al[mt], bh[g][s], bh[g][s + 2]);
                }
        }
        __syncthreads();
    }

#pragma unroll
    for (int mt = 0; mt < 4; mt++) {
        const int row = m0 + wm * 64 + mt * 16 + (lane >> 2);
#pragma unroll
        for (int nt = 0; nt < 4; nt++) {
            const int col = n0 + wn * 32 + nt * 8 + (lane & 3) * 2;
            float* p = C + (size_t)row * N + col;
            p[0] = acc[mt][nt][0]; p[1] = acc[mt][nt][1];
            float* q = C + (size_t)(row + 8) * N + col;
            q[0] = acc[mt][nt][2]; q[1] = acc[mt][nt][3];
        }
    }
}

// ---------------- RoPE + hi/lo pack ----------------
__global__ __launch_bounds__(256) void rope_pack(const float* __restrict__ cosb,
                                                 const float* __restrict__ sinb)
{
    int idx = blockIdx.x * 256 + threadIdx.x;
    if (idx < NB * NS * NH * 64) {
        int d = idx & 63, h = (idx >> 6) & 15, s = (idx >> 10) & 2047, b = idx >> 21;
        float c = cosb[s * 64 + d], sn = sinb[s * 64 + d];
        const float* qp = g_Qraw + (size_t)(b * NS + s) * (NH * NHD) + h * NHD;
        float qr = qp[d], qi = qp[64 + d];
        size_t base = ((size_t)(b * NH + h) * NS + s) * NHEFF;
        hl_store(g_Qhi, g_Qlo, base + d,       qr * (c - sn));
        hl_store(g_Qhi, g_Qlo, base + 64 + d,  qr * (c + sn));
        hl_store(g_Qhi, g_Qlo, base + 128 + d, qi);
    }
    if (idx < NB * NS * NKVH * 64) {
        int d = idx & 63, kv = (idx >> 6) & 3, s = (idx >> 8) & 2047, b = idx >> 19;
        float c = cosb[s * 64 + d], sn = sinb[s * 64 + d];
        const float* kp = g_Kraw + (size_t)(b * NS + s) * (NKVH * NHD) + kv * NHD;
        float kr = kp[d], ki = kp[64 + d];
        size_t base = ((size_t)(b * NKVH + kv) * NS + s) * NHEFF;
        hl_store(g_Khi, g_Klo, base + d,       kr * (c - sn));
        hl_store(g_Khi, g_Klo, base + 64 + d,  kr * (c + sn));
        hl_store(g_Khi, g_Klo, base + 128 + d, ki);
    }
    if (idx < NB * NS * NKVH * 128) {
        int d = idx & 127, kv = (idx >> 7) & 3, s = (idx >> 9) & 2047, b = idx >> 20;
        float v = g_Vraw[(size_t)(b * NS + s) * (NKVH * NHD) + kv * NHD + d];
        size_t di = ((size_t)(b * NKVH + kv) * NHD + d) * NS + s;   // transposed [d][s]
        hl_store(g_Vhi, g_Vlo, di, v);
    }
}

// ---------------- tensor-core windowed flash attention (unchanged, validated) ----------------
#define AQ_ROWB 400
#define AV_ROWB 144
#define AKT_B   (64*AQ_ROWB)
#define AVT_B   (128*AV_ROWB)
#define ASTG_B  (2*AKT_B + 2*AVT_B)
#define AQ_OFF  (2*ASTG_B)
#define ATTN_SMEM (AQ_OFF + 2*AKT_B)

__global__ __launch_bounds__(128) void attn_mma()
{
    extern __shared__ __align__(16) char sm[];
    const uint32_t sb = smem_u32(sm);
    const int tid = threadIdx.x, lane = tid & 31, wq = tid >> 5;
    const int qt = blockIdx.x, bh = blockIdx.y;
    const int b = bh >> 4, h = bh & 15, kv = h >> 2;
    const int qbase = qt * 64;

    const __nv_bfloat16* Qh = g_Qhi + ((size_t)(b * NH + h) * NS + qbase) * NHEFF;
    const __nv_bfloat16* Ql = g_Qlo + ((size_t)(b * NH + h) * NS + qbase) * NHEFF;
    const __nv_bfloat16* Kh = g_Khi + (size_t)(b * NKVH + kv) * NS * NHEFF;
    const __nv_bfloat16* Kl = g_Klo + (size_t)(b * NKVH + kv) * NS * NHEFF;
    const __nv_bfloat16* Vh = g_Vhi + (size_t)(b * NKVH + kv) * NHD * NS;
    const __nv_bfloat16* Vl = g_Vlo + (size_t)(b * NKVH + kv) * NHD * NS;

    for (int i = tid; i < 3072; i += 128) {
        int m = i >= 1536, idx = i - m * 1536;
        int row = idx / 24, c = idx - row * 24;
        cp16(sb + AQ_OFF + m * AKT_B + row * AQ_ROWB + c * 16,
             (m ? Ql : Qh) + (size_t)row * NHEFF + c * 8);
    }

    auto pf = [&](int kt, int buf) {
        const uint32_t st = sb + buf * ASTG_B;
        const int kb = kt * 64;
        for (int i = tid; i < 3072; i += 128) {
            int m = i >= 1536, idx = i - m * 1536;
            int row = idx / 24, c = idx - row * 24;
            cp16(st + m * AKT_B + row * AQ_ROWB + c * 16,
                 (m ? Kl : Kh) + (size_t)(kb + row) * NHEFF + c * 8);
        }
        for (int i = tid; i < 2048; i += 128) {
            int m = i >= 1024, idx = i & 1023;
            int row = idx >> 3, c = idx & 7;
            cp16(st + 2 * AKT_B + m * AVT_B + row * AV_ROWB + c * 16,
                 (m ? Vl : Vh) + (size_t)row * NS + kb + c * 8);
        }
        asm volatile("cp.async.commit_group;" ::: "memory");
    };

    const int kt0 = (qt > 16) ? (qt - 16) : 0;
    pf(kt0, 0);
    if (kt0 < qt) pf(kt0 + 1, 1);

    const int rowsel = (lane & 7) + ((lane >> 3) & 1) * 8;
    const uint32_t laQ = (uint32_t)rowsel * AQ_ROWB + (uint32_t)(lane >> 4) * 16;
    const uint32_t laV = (uint32_t)rowsel * AV_ROWB + (uint32_t)(lane >> 4) * 16;
    const uint32_t qa = sb + AQ_OFF + (uint32_t)(wq * 16) * AQ_ROWB + laQ;

    const int q0 = qbase + wq * 16 + (lane >> 2);
    const int q1 = q0 + 8;

    float mo0 = -1e30f, mo1 = -1e30f, l0 = 0.f, l1 = 0.f;
    float oacc[16][4];
#pragma unroll
    for (int i = 0; i < 16; i++)
#pragma unroll
        for (int j = 0; j < 4; j++) oacc[i][j] = 0.f;

    for (int kt = kt0; kt <= qt; kt++) {
        const int buf = (kt - kt0) & 1;
        if (kt < qt) asm volatile("cp.async.wait_group 1;" ::: "memory");
        else         asm volatile("cp.async.wait_group 0;" ::: "memory");
        __syncthreads();
        const uint32_t stK = sb + buf * ASTG_B;
        const uint32_t stV = stK + 2 * AKT_B;
        const int kbase = kt * 64;

        float sacc[8][4];
#pragma unroll
        for (int i = 0; i < 8; i++)
#pragma unroll
            for (int j = 0; j < 4; j++) sacc[i][j] = 0.f;

#pragma unroll 3
        for (int ks = 0; ks < 12; ks++) {
            uint32_t ah[4], al[4];
            ldm_x4(ah[0], ah[1], ah[2], ah[3], qa + ks * 32);
            ldm_x4(al[0], al[1], al[2], al[3], qa + AKT_B + ks * 32);
#pragma unroll
            for (int g = 0; g < 4; g++) {
                uint32_t bh4[4], bl4[4];
                uint32_t bd = stK + (uint32_t)(g * 16) * AQ_ROWB + laQ + ks * 32;
                ldm_x4(bh4[0], bh4[1], bh4[2], bh4[3], bd);
                ldm_x4(bl4[0], bl4[1], bl4[2], bl4[3], bd + AKT_B);
                mma_bf16(sacc[2 * g],     ah, bh4[0], bh4[2]);
                mma_bf16(sacc[2 * g],     ah, bl4[0], bl4[2]);
                mma_bf16(sacc[2 * g],     al, bh4[0], bh4[2]);
                mma_bf16(sacc[2 * g + 1], ah, bh4[1], bh4[3]);
                mma_bf16(sacc[2 * g + 1], ah, bl4[1], bl4[3]);
                mma_bf16(sacc[2 * g + 1], al, bh4[1], bh4[3]);
            }
        }

        float rm0 = -1e30f, rm1 = -1e30f;
#pragma unroll
        for (int j = 0; j < 8; j++) {
            int cb = kbase + j * 8 + (lane & 3) * 2;
#pragma unroll
            for (int e = 0; e < 2; e++) {
                int c = cb + e;
                float v = sacc[j][e] * SCALE_F;
                v = (c <= q0 && c + NWIN > q0) ? v : -1e30f;
                sacc[j][e] = v; rm0 = fmaxf(rm0, v);
                float w = sacc[j][e + 2] * SCALE_F;
                w = (c <= q1 && c + NWIN > q1) ? w : -1e30f;
                sacc[j][e + 2] = w; rm1 = fmaxf(rm1, w);
            }
        }
        rm0 = fmaxf(rm0, __shfl_xor_sync(0xffffffffu, rm0, 1));
        rm0 = fmaxf(rm0, __shfl_xor_sync(0xffffffffu, rm0, 2));
        rm1 = fmaxf(rm1, __shfl_xor_sync(0xffffffffu, rm1, 1));
        rm1 = fmaxf(rm1, __shfl_xor_sync(0xffffffffu, rm1, 2));
        float mn0 = fmaxf(mo0, rm0), f0 = __expf(mo0 - mn0); mo0 = mn0;
        float mn1 = fmaxf(mo1, rm1), f1 = __expf(mo1 - mn1); mo1 = mn1;
        float rs0 = 0.f, rs1 = 0.f;
#pragma unroll
        for (int j = 0; j < 8; j++) {
#pragma unroll
            for (int e = 0; e < 2; e++) {
                float p = (sacc[j][e] > -1e29f) ? __expf(sacc[j][e] - mn0) : 0.f;
                sacc[j][e] = p; rs0 += p;
                float r = (sacc[j][e + 2] > -1e29f) ? __expf(sacc[j][e + 2] - mn1) : 0.f;
                sacc[j][e + 2] = r; rs1 += r;
            }
        }
        rs0 += __shfl_xor_sync(0xffffffffu, rs0, 1);
        rs0 += __shfl_xor_sync(0xffffffffu, rs0, 2);
        rs1 += __shfl_xor_sync(0xffffffffu, rs1, 1);
        rs1 += __shfl_xor_sync(0xffffffffu, rs1, 2);
        l0 = l0 * f0 + rs0;
        l1 = l1 * f1 + rs1;
#pragma unroll
        for (int nt = 0; nt < 16; nt++) {
            oacc[nt][0] *= f0; oacc[nt][1] *= f0;
            oacc[nt][2] *= f1; oacc[nt][3] *= f1;
        }

#pragma unroll
        for (int ks = 0; ks < 4; ks++) {
            uint32_t ph[4], pl[4];
            packhl(sacc[2 * ks][0],     sacc[2 * ks][1],     ph[0], pl[0]);
            packhl(sacc[2 * ks][2],     sacc[2 * ks][3],     ph[1], pl[1]);
            packhl(sacc[2 * ks + 1][0], sacc[2 * ks + 1][1], ph[2], pl[2]);
            packhl(sacc[2 * ks + 1][2], sacc[2 * ks + 1][3], ph[3], pl[3]);
#pragma unroll
            for (int g = 0; g < 8; g++) {
                uint32_t vh4[4], vl4[4];
                uint32_t vd = stV + (uint32_t)(g * 16) * AV_ROWB + laV + ks * 32;
                ldm_x4(vh4[0], vh4[1], vh4[2], vh4[3], vd);
                ldm_x4(vl4[0], vl4[1], vl4[2], vl4[3], vd + AVT_B);
                mma_bf16(oacc[2 * g],     ph, vh4[0], vh4[2]);
                mma_bf16(oacc[2 * g],     ph, vl4[0], vl4[2]);
                mma_bf16(oacc[2 * g],     pl, vh4[0], vh4[2]);
                mma_bf16(oacc[2 * g + 1], ph, vh4[1], vh4[3]);
                mma_bf16(oacc[2 * g + 1], ph, vl4[1], vl4[3]);
                mma_bf16(oacc[2 * g + 1], pl, vh4[1], vh4[3]);
            }
        }
        __syncthreads();
        if (kt + 2 <= qt) pf(kt + 2, buf);
    }

    const float i0 = 1.f / l0, i1 = 1.f / l1;
    const size_t ro0 = (size_t)(b * NS + q0) * (NH * NHD) + h * NHD;
    const size_t ro1 = ro0 + (size_t)8 * (NH * NHD);
#pragma unroll
    for (int nt = 0; nt < 16; nt++) {
        const int col = nt * 8 + (lane & 3) * 2;
        uint32_t hi, lo;
        packhl(oacc[nt][0] * i0, oacc[nt][1] * i0, hi, lo);
        *(uint32_t*)&g_Ohi[ro0 + col] = hi;
        *(uint32_t*)&g_Olo[ro0 + col] = lo;
        packhl(oacc[nt][2] * i1, oacc[nt][3] * i1, hi, lo);
        *(uint32_t*)&g_Ohi[ro1 + col] = hi;
        *(uint32_t*)&g_Olo[ro1 + col] = lo;
    }
}

// ---------------- launch ----------------
extern "C" void kernel_launch(void* const* d_in, const int* in_sizes, int n_in,
                              void* d_out, int out_size)
{
    (void)in_sizes; (void)n_in; (void)out_size;
    const float* x    = (const float*)d_in[0];
    const float* cosb = (const float*)d_in[1];
    const float* sinb = (const float*)d_in[2];
    const float* wq   = (const float*)d_in[5];
    const float* wk   = (const float*)d_in[6];
    const float* wv   = (const float*)d_in[7];
    const float* wo   = (const float*)d_in[8];
    float* out = (float*)d_out;

    float *Qraw, *Kraw, *Vraw;
    __nv_bfloat16 *xhi, *xlo, *Ohi, *Olo;
    __nv_bfloat16 *wqthi, *wqtlo, *wkthi, *wktlo, *wvthi, *wvtlo, *wothi, *wotlo;
    cudaGetSymbolAddress((void**)&Qraw, g_Qraw);
    cudaGetSymbolAddress((void**)&Kraw, g_Kraw);
    cudaGetSymbolAddress((void**)&Vraw, g_Vraw);
    cudaGetSymbolAddress((void**)&xhi,  g_xhi);
    cudaGetSymbolAddress((void**)&xlo,  g_xlo);
    cudaGetSymbolAddress((void**)&Ohi,  g_Ohi);
    cudaGetSymbolAddress((void**)&Olo,  g_Olo);
    cudaGetSymbolAddress((void**)&wqthi, g_wqthi);
    cudaGetSymbolAddress((void**)&wqtlo, g_wqtlo);
    cudaGetSymbolAddress((void**)&wkthi, g_wkthi);
    cudaGetSymbolAddress((void**)&wktlo, g_wktlo);
    cudaGetSymbolAddress((void**)&wvthi, g_wvthi);
    cudaGetSymbolAddress((void**)&wvtlo, g_wvtlo);
    cudaGetSymbolAddress((void**)&wothi, g_wothi);
    cudaGetSymbolAddress((void**)&wotlo, g_wotlo);

    static bool attr_done = false;
    if (!attr_done) {
        cudaFuncSetAttribute(gemm_mma, cudaFuncAttributeMaxDynamicSharedMemorySize, GEMM_SMEM);
        cudaFuncSetAttribute(attn_mma, cudaFuncAttributeMaxDynamicSharedMemorySize, ATTN_SMEM);
        attr_done = true;
    }

    // operand conversion
    cvt_hi_lo<<<(NM * NDIM + 255) / 256, 256>>>(x, xhi, xlo, NM * NDIM);
    cvt_w_t<<<dim3((NH * NHD) / 32, NDIM / 32),  256>>>(wq, wqthi, wqtlo, NDIM, NH * NHD);
    cvt_w_t<<<dim3((NKVH * NHD) / 32, NDIM / 32), 256>>>(wk, wkthi, wktlo, NDIM, NKVH * NHD);
    cvt_w_t<<<dim3((NKVH * NHD) / 32, NDIM / 32), 256>>>(wv, wvthi, wvtlo, NDIM, NKVH * NHD);
    cvt_w_t<<<dim3(NDIM / 32, (NH * NHD) / 32),  256>>>(wo, wothi, wotlo, NH * NHD, NDIM);

    // QKV projections
    gemm_mma<<<dim3((NH * NHD) / 128,   NM / 128), 256, GEMM_SMEM>>>(xhi, xlo, wqthi, wqtlo, Qraw, NDIM, NH * NHD);
    gemm_mma<<<dim3((NKVH * NHD) / 128, NM / 128), 256, GEMM_SMEM>>>(xhi, xlo, wkthi, wktlo, Kraw, NDIM, NKVH * NHD);
    gemm_mma<<<dim3((NKVH * NHD) / 128, NM / 128), 256, GEMM_SMEM>>>(xhi, xlo, wvthi, wvtlo, Vraw, NDIM, NKVH * NHD);

    // RoPE + hi/lo pack
    rope_pack<<<(NB * NS * NH * 64 + 255) / 256, 256>>>(cosb, sinb);

    // tensor-core windowed attention (writes Ohi/Olo directly)
    attn_mma<<<dim3(NS / 64, NB * NH), 128, ATTN_SMEM>>>();

    // output projection
    gemm_mma<<<dim3(NDIM / 128, NM / 128), 256, GEMM_SMEM>>>(Ohi, Olo, wothi, wotlo, out, NH * NHD, NDIM);
}